// round 14
// baseline (speedup 1.0000x reference)
#include <cuda_runtime.h>
#include <cuda_bf16.h>
#include <cstdint>

typedef unsigned long long ull;
typedef uint32_t u32;

#define BB  4
#define CC_ 256
#define DD  64
#define NN  4096
#define TI  128
#define TJ  64
#define NTILES (NN/TJ)

// ---------------- scratch: fragment-shuffled operand tensors ----------------
// q: [B][32 itile][8 rb][4 kk][32 lane][4 u32]   (A-frags, bf16x2 pairs, hi/lo)
// k: [B][64 jt][8 jb][4 kk][32 lane][2 u32]      (B-frags, hi/lo)
// v: [B][64 jt][4 kk][32 cb][32 lane][2 u32]     (B-frags)
__device__ u32 g_qfh[(size_t)BB*32*4096];
__device__ u32 g_qfl[(size_t)BB*32*4096];
__device__ u32 g_kfh[(size_t)BB*64*2048];
__device__ u32 g_kfl[(size_t)BB*64*2048];
__device__ u32 g_vf [(size_t)BB*64*8192];

// ---------------- helpers ----------------
__device__ __forceinline__ u32 smem_u32p(const void* p){
  u32 a; asm("{ .reg .u64 t; cvta.to.shared.u64 t, %1; cvt.u32.u64 %0, t; }":"=r"(a):"l"(p)); return a;
}
#define CP16(dst,src) asm volatile("cp.async.ca.shared.global [%0], [%1], 16;"::"r"(dst),"l"(src))
#define CP_COMMIT()  asm volatile("cp.async.commit_group;":::"memory")
#define CP_WAIT0()   asm volatile("cp.async.wait_group 0;":::"memory")

__device__ __forceinline__ u32 packbf(float lo, float hi){
  u32 r; asm("cvt.rn.bf16x2.f32 %0, %1, %2;" : "=r"(r) : "f"(hi), "f"(lo)); return r;
}
__device__ __forceinline__ u32 pack2h(__nv_bfloat16 a, __nv_bfloat16 b){
  return (u32)__bfloat16_as_ushort(a) | ((u32)__bfloat16_as_ushort(b) << 16);
}
// m16n8k16 bf16 HMMA (sm_80 base-PTX)
__device__ __forceinline__ void mma16(float* c, const u32* a, const u32* b){
  asm volatile("mma.sync.aligned.m16n8k16.row.col.f32.bf16.bf16.f32 "
    "{%0,%1,%2,%3}, {%4,%5,%6,%7}, {%8,%9}, {%0,%1,%2,%3};"
    : "+f"(c[0]),"+f"(c[1]),"+f"(c[2]),"+f"(c[3])
    : "r"(a[0]),"r"(a[1]),"r"(a[2]),"r"(a[3]), "r"(b[0]),"r"(b[1]));
}
// exp on the FFMA pipe
__device__ __forceinline__ float fexp(float s){
  float t = s * 1.4426950408889634f;
  t = fmaxf(t, -126.0f); t = fminf(t, 126.0f);
  float r  = t + 12582912.0f;
  float fn = r - 12582912.0f;
  float f  = t - fn;
  float p = 1.3333558146e-3f;
  p = fmaf(p, f, 9.6181291057e-3f);
  p = fmaf(p, f, 5.5504108664e-2f);
  p = fmaf(p, f, 2.4022650696e-1f);
  p = fmaf(p, f, 6.9314718056e-1f);
  p = fmaf(p, f, 1.0f);
  int ni = __float_as_int(r) - 0x4B400000;
  return __int_as_float(__float_as_int(p) + (ni << 23));
}

// ---- packed f32x2 for projections ----
__device__ __forceinline__ ull pk2(float lo, float hi){
  ull r; asm("mov.b64 %0,{%1,%2};" : "=l"(r) : "f"(lo), "f"(hi)); return r;
}
__device__ __forceinline__ void upk2(ull v, float& lo, float& hi){
  asm("mov.b64 {%0,%1},%2;" : "=f"(lo), "=f"(hi) : "l"(v));
}
__device__ __forceinline__ void ffma2(ull& d, ull a, ull b){
  asm("fma.rn.f32x2 %0,%1,%2,%0;" : "+l"(d) : "l"(a), "l"(b));
}

// ============================================================================
// Projection. MODE 0 -> q frags hi/lo; 1 -> k frags hi/lo; 2 -> v frags.
// ============================================================================
template<int MODE>
__global__ void __launch_bounds__(256) proj_kernel(
    const float* __restrict__ W, const float* __restrict__ bias,
    const float* __restrict__ x)
{
  __shared__ float Ws[64][17];
  __shared__ float Xs[16][128];

  const int t = threadIdx.x;
  const int b = blockIdx.z;
  const int nbase = blockIdx.x * 128;
  const int mbase = blockIdx.y * 64;
  const float* xb = x + (size_t)b * CC_ * NN;

  ull acc[4][4];
  #pragma unroll
  for (int r = 0; r < 4; r++)
    #pragma unroll
    for (int q = 0; q < 4; q++) acc[r][q] = 0ull;

  const int m0 = (t & 15) * 4;
  const int n0 = (t >> 4) * 8;

  for (int cc = 0; cc < CC_; cc += 16){
    {
      int m = t >> 2, cp = (t & 3) * 4;
      float4 w4 = *(const float4*)(W + (size_t)(mbase + m) * CC_ + cc + cp);
      Ws[m][cp] = w4.x; Ws[m][cp+1] = w4.y; Ws[m][cp+2] = w4.z; Ws[m][cp+3] = w4.w;
    }
    {
      int cp = t >> 4, np = (t & 15) * 8;
      const float* src = xb + (size_t)(cc + cp) * NN + nbase + np;
      *(float4*)&Xs[cp][np]     = *(const float4*)src;
      *(float4*)&Xs[cp][np + 4] = *(const float4*)(src + 4);
    }
    __syncthreads();
    #pragma unroll
    for (int cp = 0; cp < 16; cp++){
      ulonglong2 xa = *(const ulonglong2*)&Xs[cp][n0];
      ulonglong2 xc = *(const ulonglong2*)&Xs[cp][n0 + 4];
      ull xv0 = xa.x, xv1 = xa.y, xv2 = xc.x, xv3 = xc.y;
      #pragma unroll
      for (int r = 0; r < 4; r++){
        float w = Ws[m0 + r][cp];
        ull wb = pk2(w, w);
        ffma2(acc[r][0], wb, xv0); ffma2(acc[r][1], wb, xv1);
        ffma2(acc[r][2], wb, xv2); ffma2(acc[r][3], wb, xv3);
      }
    }
    __syncthreads();
  }

  float av[4][8];
  #pragma unroll
  for (int r = 0; r < 4; r++){
    float bb = bias[mbase + m0 + r];
    #pragma unroll
    for (int q = 0; q < 4; q++){
      float lo, hi; upk2(acc[r][q], lo, hi);
      av[r][2*q]   = lo + bb;
      av[r][2*q+1] = hi + bb;
    }
  }

  if (MODE == 2){
    #pragma unroll
    for (int rr = 0; rr < 4; rr++){
      int c = mbase + m0 + rr;
      int cb = c >> 3, lrv = c & 7;
      #pragma unroll
      for (int np = 0; np < 4; np++){
        int nn = np * 2;
        u32 pv = pack2h(__float2bfloat16(av[rr][nn]), __float2bfloat16(av[rr][nn+1]));
        int j = nbase + n0 + nn;
        int jt = j >> 6, j6 = j & 63;
        int kk = j6 >> 4, rg = (j6 >> 3) & 1, lc = (j6 & 7) >> 1;
        size_t idx = (((((size_t)b*64 + jt)*4 + kk)*32 + cb)*32 + (lrv*4 + lc))*2 + rg;
        g_vf[idx] = pv;
      }
    }
  } else {
    u32* dh = (MODE == 0) ? g_qfh : g_kfh;
    u32* dl = (MODE == 0) ? g_qfl : g_kfl;
    #pragma unroll
    for (int nn = 0; nn < 8; nn++){
      int i = nbase + n0 + nn;
      #pragma unroll
      for (int p = 0; p < 2; p++){
        int d = m0 + 2*p;
        float q0 = av[2*p][nn], q1 = av[2*p+1][nn];
        __nv_bfloat16 h0 = __float2bfloat16(q0);
        __nv_bfloat16 h1 = __float2bfloat16(q1);
        float l0 = q0 - __bfloat162float(h0);
        float l1 = q1 - __bfloat162float(h1);
        u32 uh = pack2h(h0, h1);
        u32 ul = pack2h(__float2bfloat16(l0), __float2bfloat16(l1));
        int kk = d >> 4, lc = (d >> 1) & 3;
        if (MODE == 0){
          int itile = i >> 7, rb = (i >> 4) & 7, lr = i & 7;
          int e = ((i >> 3) & 1) | (((d >> 3) & 1) << 1);
          size_t idx = (((((size_t)b*32 + itile)*8 + rb)*4 + kk)*32 + (lr*4 + lc))*4 + e;
          dh[idx] = uh; dl[idx] = ul;
        } else {
          int jt = i >> 6, jb = (i >> 3) & 7, lr = i & 7;
          int rg = (d >> 3) & 1;
          size_t idx = (((((size_t)b*64 + jt)*8 + jb)*4 + kk)*32 + (lr*4 + lc))*2 + rg;
          dh[idx] = uh; dl[idx] = ul;
        }
      }
    }
  }
}

// ============================================================================
// Attention: deferred-PV pipeline. One __syncthreads per tile. Within each
// inter-sync window: QK(tt) MMAs + PV(tt-1) MMAs + exp(tt) FFMAs, so warps
// drift and the exp phase overlaps tensor work of other warps.
// Buffers: K 2-stage, V 3-stage (prefetch (tt+1)%3 vs PV read (tt-1)%3),
// PSF 2-stage (write tt&1, read (tt-1)&1). K prefetch mid-iteration.
// SMEM (u32): QFH 4096 | QFL 4096 | KF 2x4096 | VF 3x8192 | PSF 2x4096 | PT LS
// ============================================================================
#define O_QFH 0
#define O_QFL 4096
#define O_KF  8192
#define O_VF  16384
#define O_PSF 40960
#define O_PT  49152
#define O_LS  49408
#define SMEM_U32 49536

__device__ __forceinline__ void do_pv(const u32* PSFs, const u32* VFs,
    float (*o)[8][4], int rbO, int cbb, int lane){
  #pragma unroll
  for (int kk = 0; kk < 4; kk++){
    u32 af[4][4];
    #pragma unroll
    for (int fi = 0; fi < 4; fi++){
      uint4 a = *(const uint4*)&PSFs[(((rbO+fi)*4 + kk)*32 + lane)*4];
      af[fi][0] = a.x; af[fi][1] = a.y; af[fi][2] = a.z; af[fi][3] = a.w;
    }
    #pragma unroll
    for (int fc = 0; fc < 8; fc++){
      uint2 bb = *(const uint2*)&VFs[((kk*32 + cbb + fc)*32 + lane)*2];
      u32 bf2[2] = {bb.x, bb.y};
      #pragma unroll
      for (int fi = 0; fi < 4; fi++)
        mma16(o[fi][fc], af[fi], bf2);
    }
  }
}

__global__ void __launch_bounds__(256) attn_kernel(
    const float* __restrict__ x, const float* __restrict__ gamma_p,
    float* __restrict__ out)
{
  extern __shared__ u32 smu[];
  u32* QFH = smu + O_QFH;
  u32* QFL = smu + O_QFL;
  u32* KF  = smu + O_KF;
  u32* VF  = smu + O_VF;
  u32* PSF = smu + O_PSF;
  float* PT = (float*)(smu + O_PT);
  float* LS = (float*)(smu + O_LS);

  const int t = threadIdx.x;
  const int lane = t & 31;
  const int w = t >> 5;
  const int lr = lane >> 2, lc = lane & 3;
  const int b = blockIdx.y;
  const int itile = blockIdx.x;
  const int ibase = itile * TI;

  const int rbase  = (w & 3) * 2;   // QK A rows
  const int jbbase = (w >> 2) * 4;  // QK B cols
  const int kkS    = (w >> 2) * 2;  // PSF kk base
  const int rbO    = (w & 1) * 4;   // PV A rows
  const int cbb    = (w >> 1) * 8;  // PV B cols

  const u32 kf_s = smem_u32p(KF);
  const u32 vf_s = smem_u32p(VF);

  // ---- one-time Q fragment load ----
  {
    const u32* sh = g_qfh + ((size_t)(b*32 + itile))*4096 + t*16;
    const u32* sl = g_qfl + ((size_t)(b*32 + itile))*4096 + t*16;
    #pragma unroll
    for (int u = 0; u < 4; u++){
      *(uint4*)&QFH[t*16 + u*4] = *(const uint4*)(sh + u*4);
      *(uint4*)&QFL[t*16 + u*4] = *(const uint4*)(sl + u*4);
    }
  }

  // ---- prefetch tile 0: K -> buf 0, V -> stage 0 ----
  {
    const u32* kh = g_kfh + ((size_t)(b*64 + 0))*2048 + t*8;
    const u32* kl = g_kfl + ((size_t)(b*64 + 0))*2048 + t*8;
    const u32* vv = g_vf  + ((size_t)(b*64 + 0))*8192 + t*32;
    CP16(kf_s + (t*8)*4, kh); CP16(kf_s + (t*8+4)*4, kh+4);
    CP16(kf_s + (2048 + t*8)*4, kl); CP16(kf_s + (2048 + t*8+4)*4, kl+4);
    #pragma unroll
    for (int u = 0; u < 8; u++) CP16(vf_s + (t*32 + u*4)*4, vv + u*4);
    CP_COMMIT();
  }

  float o[4][8][4];
  #pragma unroll
  for (int fi = 0; fi < 4; fi++)
    #pragma unroll
    for (int fc = 0; fc < 8; fc++)
      #pragma unroll
      for (int e = 0; e < 4; e++) o[fi][fc][e] = 0.f;
  float lp[2][2] = {{0.f,0.f},{0.f,0.f}};

  int stg_nxt = 1;   // (tt+1) % 3
  int stg_prv = 2;   // (tt-1) % 3  (unused at tt=0)

  for (int tt = 0; tt < NTILES; tt++){
    CP_WAIT0();
    __syncthreads();                          // the ONLY sync per tile

    // prefetch V(tt+1) -> stage (tt+1)%3
    if (tt + 1 < NTILES){
      const u32* vv = g_vf + ((size_t)(b*64 + tt+1))*8192 + t*32;
      u32 vb = vf_s + (u32)stg_nxt * 8192u * 4u;
      #pragma unroll
      for (int u = 0; u < 8; u++) CP16(vb + (t*32 + u*4)*4, vv + u*4);
      CP_COMMIT();
    }

    // ---- QK(tt): 3 bf16 passes ----
    const u32* KFs = KF + (tt & 1) * 4096;
    float s[2][4][4];
    #pragma unroll
    for (int fi = 0; fi < 2; fi++)
      #pragma unroll
      for (int fj = 0; fj < 4; fj++)
        #pragma unroll
        for (int e = 0; e < 4; e++) s[fi][fj][e] = 0.f;

    #pragma unroll
    for (int pass = 0; pass < 3; pass++){
      const u32* Ab = (pass == 2) ? QFL : QFH;
      const u32* Bb = KFs + ((pass == 1) ? 2048 : 0);
      #pragma unroll
      for (int kk = 0; kk < 4; kk++){
        uint4 a0 = *(const uint4*)&Ab[((rbase+0)*4 + kk)*128 + lane*4];
        uint4 a1 = *(const uint4*)&Ab[((rbase+1)*4 + kk)*128 + lane*4];
        u32 af0[4] = {a0.x, a0.y, a0.z, a0.w};
        u32 af1[4] = {a1.x, a1.y, a1.z, a1.w};
        #pragma unroll
        for (int fj = 0; fj < 4; fj++){
          uint2 bb = *(const uint2*)&Bb[((jbbase+fj)*4 + kk)*64 + lane*2];
          u32 bf2[2] = {bb.x, bb.y};
          mma16(s[0][fj], af0, bf2);
          mma16(s[1][fj], af1, bf2);
        }
      }
    }

    // prefetch K(tt+1) -> buf (tt+1)&1 (overlaps PV + exp below)
    if (tt + 1 < NTILES){
      const u32* kh = g_kfh + ((size_t)(b*64 + tt+1))*2048 + t*8;
      const u32* kl = g_kfl + ((size_t)(b*64 + tt+1))*2048 + t*8;
      u32 kb = kf_s + (u32)((tt+1) & 1) * 4096u * 4u;
      CP16(kb + (t*8)*4, kh); CP16(kb + (t*8+4)*4, kh+4);
      CP16(kb + (2048 + t*8)*4, kl); CP16(kb + (2048 + t*8+4)*4, kl+4);
      CP_COMMIT();
    }

    // ---- PV(tt-1): independent of s -> overlaps exp below in the window ----
    if (tt > 0)
      do_pv(PSF + ((tt-1) & 1) * 4096, VF + stg_prv * 8192, o, rbO, cbb, lane);

    // ---- exp(tt) + pack + store PSF[tt&1]; l partials in regs ----
    u32* PSFw = PSF + (tt & 1) * 4096;
    #pragma unroll
    for (int fi = 0; fi < 2; fi++){
      #pragma unroll
      for (int fjp = 0; fjp < 2; fjp++){
        int fj0 = fjp * 2;
        float p00 = fexp(s[fi][fj0][0]),   p01 = fexp(s[fi][fj0][1]);
        float p02 = fexp(s[fi][fj0][2]),   p03 = fexp(s[fi][fj0][3]);
        float p10 = fexp(s[fi][fj0+1][0]), p11 = fexp(s[fi][fj0+1][1]);
        float p12 = fexp(s[fi][fj0+1][2]), p13 = fexp(s[fi][fj0+1][3]);
        lp[fi][0] += (p00 + p01) + (p10 + p11);
        lp[fi][1] += (p02 + p03) + (p12 + p13);
        uint4 pk;
        pk.x = packbf(p00, p01); pk.y = packbf(p02, p03);
        pk.z = packbf(p10, p11); pk.w = packbf(p12, p13);
        *(uint4*)&PSFw[(((rbase+fi)*4 + kkS + fjp)*32 + lane)*4] = pk;
      }
    }

    stg_prv = stg_nxt == 0 ? 1 : (stg_nxt == 1 ? 2 : 0); // (tt)%3 -> becomes prv next iter
    stg_prv = tt % 3;          // simpler: prv for next iter = tt%3
    stg_nxt = (tt + 2) % 3;    // nxt for next iter = (tt+2)%3
  }

  __syncthreads();   // all PSF[(NT-1)&1] writes visible
  do_pv(PSF + ((NTILES-1) & 1) * 4096, VF + ((NTILES-1) % 3) * 8192, o, rbO, cbb, lane);

  // ---- l reduction ----
  #pragma unroll
  for (int fi = 0; fi < 2; fi++)
    #pragma unroll
    for (int rh = 0; rh < 2; rh++){
      float v = lp[fi][rh];
      v += __shfl_xor_sync(0xffffffffu, v, 1);
      v += __shfl_xor_sync(0xffffffffu, v, 2);
      if (lc == 0)
        PT[(w >> 2)*128 + (w & 3)*32 + fi*16 + rh*8 + lr] = v;
    }
  __syncthreads();
  if (t < 128) LS[t] = PT[t] + PT[128 + t];
  __syncthreads();

  // ---- epilogue: out[c][i] = gamma * O[i][c] / l[i] + x[c][i] ----
  const float gam = gamma_p[0];
  const float* xg = x   + (size_t)b * CC_ * NN;
  float*       og = out + (size_t)b * CC_ * NN;
  const int wiO = (w & 1) * 64, wcO = (w >> 1) * 64;
  #pragma unroll
  for (int fi = 0; fi < 4; fi++){
    int il = wiO + fi*16 + lr;
    float li0 = gam / LS[il];
    float li1 = gam / LS[il + 8];
    int i0g = ibase + il;
    #pragma unroll
    for (int fc = 0; fc < 8; fc++){
      int c0 = wcO + fc*8 + 2*lc;
      size_t r0 = (size_t)c0 * NN;
      size_t r1 = r0 + NN;
      og[r0 + i0g]     = fmaf(o[fi][fc][0], li0, xg[r0 + i0g]);
      og[r1 + i0g]     = fmaf(o[fi][fc][1], li0, xg[r1 + i0g]);
      og[r0 + i0g + 8] = fmaf(o[fi][fc][2], li1, xg[r0 + i0g + 8]);
      og[r1 + i0g + 8] = fmaf(o[fi][fc][3], li1, xg[r1 + i0g + 8]);
    }
  }
}

// ============================================================================
extern "C" void kernel_launch(void* const* d_in, const int* in_sizes, int n_in,
                              void* d_out, int out_size)
{
  (void)in_sizes; (void)n_in; (void)out_size;
  const float* x  = (const float*)d_in[0];
  const float* Wq = (const float*)d_in[1];
  const float* bq = (const float*)d_in[2];
  const float* Wk = (const float*)d_in[3];
  const float* bk = (const float*)d_in[4];
  const float* Wv = (const float*)d_in[5];
  const float* bv = (const float*)d_in[6];
  const float* gm = (const float*)d_in[7];
  float* out = (float*)d_out;

  const int shmem = SMEM_U32 * 4;   // 198144 B
  cudaFuncSetAttribute(attn_kernel, cudaFuncAttributeMaxDynamicSharedMemorySize, shmem);

  proj_kernel<0><<<dim3(NN/128, 1, BB), 256>>>(Wq, bq, x);
  proj_kernel<1><<<dim3(NN/128, 1, BB), 256>>>(Wk, bk, x);
  proj_kernel<2><<<dim3(NN/128, 4, BB), 256>>>(Wv, bv, x);
  attn_kernel<<<dim3(NN/TI, BB), 256, shmem>>>(x, gm, out);
}